// round 14
// baseline (speedup 1.0000x reference)
#include <cuda_runtime.h>
#include <cuda_fp16.h>
#include <cstdint>

// GNN_82592221102580 — fused per 64x64 batch tile (nc = 4096):
//   E = exp(X); Sinv[i] = 1/sum_k E[k][i]
//   Xn = LayerNorm(X) (ddof=1)
//   node[i][j] = Sinv[i] * sum_k E[k][i]*Xn[k][j]   <- mma.m16n8k16 fp16 (f32 acc)
//   out = relu(node @ W)                            <- mma.m16n8k16 fp16 (f32 acc)
//
// 2 batch tiles per CTA (256 thr), 4 warps per tile each computing 32x32.
// Operands in half2-packed, XOR-swizzled 8KB buffers; fragment loads via
// ldmatrix.m8n8.x4 (per-k-step address update = XOR s<<5).
// ND (node) overlays the ET buffer after GEMM1 (extra barrier) -> 45KB smem;
// __launch_bounds__(256,4) -> 4 CTAs/SM.

__device__ __forceinline__ int swz(int i, int kp) {          // word index
    return i * 32 + (kp ^ ((((i >> 3) ^ i) & 7) << 2));
}
__device__ __forceinline__ int swzb(int row, int kp) {       // byte offset
    return row * 128 + 4 * (kp ^ ((((row >> 3) ^ row) & 7) << 2));
}

// pack (lo, hi) -> u32, lo in bits[15:0]. PTX cvt.rn.f16x2.f32 d,a,b puts b low.
__device__ __forceinline__ uint32_t pack_h2(float lo, float hi) {
    uint32_t r;
    asm("cvt.rn.f16x2.f32 %0, %1, %2;" : "=r"(r) : "f"(hi), "f"(lo));
    return r;
}

__device__ __forceinline__ void ldm_x4(uint32_t& r0, uint32_t& r1, uint32_t& r2,
                                       uint32_t& r3, uint32_t addr) {
    asm volatile("ldmatrix.sync.aligned.m8n8.x4.shared.b16 {%0,%1,%2,%3}, [%4];"
                 : "=r"(r0), "=r"(r1), "=r"(r2), "=r"(r3) : "r"(addr));
}

__device__ __forceinline__ void mma_f16(float d[4], const uint32_t a[4],
                                        uint32_t b0, uint32_t b1) {
    asm volatile(
        "mma.sync.aligned.m16n8k16.row.col.f32.f16.f16.f32 "
        "{%0,%1,%2,%3}, {%4,%5,%6,%7}, {%8,%9}, {%0,%1,%2,%3};"
        : "+f"(d[0]), "+f"(d[1]), "+f"(d[2]), "+f"(d[3])
        : "r"(a[0]), "r"(a[1]), "r"(a[2]), "r"(a[3]), "r"(b0), "r"(b1));
}

// dynamic smem layout (bytes)
#define OF_ET 0          // [2][2048] u32  ET packed; ND overlays after GEMM1
#define OF_XN 16384      // [2][2048] u32  Xn^T packed
#define OF_WT 32768      // [2048]    u32  W^T packed
#define OF_SP 40960      // [2][8][64] f32 colsum partials
#define OF_SI 45056      // [2][64]   f32  Sinv
#define OF_A2 45568      // [64] f32
#define OF_B2 45824      // [64] f32
#define SMEM_BYTES 46080

__global__ __launch_bounds__(256, 4) void gnn_fused_kernel(
    const float* __restrict__ X,
    const float* __restrict__ W,
    const float* __restrict__ a2,
    const float* __restrict__ b2,
    float* __restrict__ out)
{
    extern __shared__ __align__(16) char sm[];
    uint32_t* ET = (uint32_t*)(sm + OF_ET);
    uint32_t* XN = (uint32_t*)(sm + OF_XN);
    uint32_t* WT = (uint32_t*)(sm + OF_WT);
    float*    Sp = (float*)(sm + OF_SP);
    float*    Si = (float*)(sm + OF_SI);
    float*   a2s = (float*)(sm + OF_A2);
    float*   b2s = (float*)(sm + OF_B2);

    const uint32_t smb = (uint32_t)__cvta_generic_to_shared(sm);

    const int t    = threadIdx.x;
    const int warp = t >> 5;
    const int lane = t & 31;
    const int R    = t >> 3;   // row-pair 0..31 (owns rows 2R, 2R+1)
    const int C    = t & 7;    // col group (cols 4C..4C+3 and +32)

    if (t < 64) { a2s[t] = a2[t]; b2s[t] = b2[t]; }

    // ---- W -> WT (packed, swizzled) ----
    {
        float w0[8], w1[8];
        float4 v;
        v = *(const float4*)(W + (2*R)*64     + 4*C); w0[0]=v.x; w0[1]=v.y; w0[2]=v.z; w0[3]=v.w;
        v = *(const float4*)(W + (2*R)*64 +32 + 4*C); w0[4]=v.x; w0[5]=v.y; w0[6]=v.z; w0[7]=v.w;
        v = *(const float4*)(W + (2*R+1)*64   + 4*C); w1[0]=v.x; w1[1]=v.y; w1[2]=v.z; w1[3]=v.w;
        v = *(const float4*)(W + (2*R+1)*64+32+ 4*C); w1[4]=v.x; w1[5]=v.y; w1[6]=v.z; w1[7]=v.w;
#pragma unroll
        for (int q = 0; q < 8; q++) {
            const int c = 4*C + (q & 3) + (q >> 2) * 32;
            WT[swz(c, R)] = pack_h2(w0[q], w1[q]);
        }
    }
    __syncthreads();   // a2s/b2s visible

    // ---- Phase A per tile: X -> E^T, Xn^T (packed) + column-sum partials ----
#pragma unroll
    for (int tile = 0; tile < 2; tile++) {
        const float* Xb = X + (size_t)(2 * blockIdx.x + tile) * 4096u;
        float x0[8], x1[8];
        float4 v;
        v = *(const float4*)(Xb + (2*R)*64      + 4*C); x0[0]=v.x; x0[1]=v.y; x0[2]=v.z; x0[3]=v.w;
        v = *(const float4*)(Xb + (2*R)*64 + 32 + 4*C); x0[4]=v.x; x0[5]=v.y; x0[6]=v.z; x0[7]=v.w;
        v = *(const float4*)(Xb + (2*R+1)*64    + 4*C); x1[0]=v.x; x1[1]=v.y; x1[2]=v.z; x1[3]=v.w;
        v = *(const float4*)(Xb + (2*R+1)*64+32 + 4*C); x1[4]=v.x; x1[5]=v.y; x1[6]=v.z; x1[7]=v.w;

        float s0=0.f, ss0=0.f, s1=0.f, ss1=0.f;
#pragma unroll
        for (int q = 0; q < 8; q++) {
            s0 += x0[q]; ss0 += x0[q]*x0[q];
            s1 += x1[q]; ss1 += x1[q]*x1[q];
        }
#pragma unroll
        for (int m = 1; m <= 4; m <<= 1) {
            s0  += __shfl_xor_sync(0xFFFFFFFFu, s0,  m);
            ss0 += __shfl_xor_sync(0xFFFFFFFFu, ss0, m);
            s1  += __shfl_xor_sync(0xFFFFFFFFu, s1,  m);
            ss1 += __shfl_xor_sync(0xFFFFFFFFu, ss1, m);
        }
        const float mean0 = s0 * (1.0f/64.0f);
        const float mean1 = s1 * (1.0f/64.0f);
        float var0 = fmaxf((ss0 - 64.0f*mean0*mean0) * (1.0f/63.0f), 0.0f);
        float var1 = fmaxf((ss1 - 64.0f*mean1*mean1) * (1.0f/63.0f), 0.0f);
        const float rv0 = 1.0f / (sqrtf(var0) + 1e-6f);
        const float rv1 = 1.0f / (sqrtf(var1) + 1e-6f);

        uint32_t* ETt = ET + tile * 2048;
        uint32_t* XNt = XN + tile * 2048;
        float pc[8];
#pragma unroll
        for (int q = 0; q < 8; q++) {
            const int c = 4*C + (q & 3) + (q >> 2) * 32;
            const float e0 = __expf(x0[q]);
            const float e1 = __expf(x1[q]);
            pc[q] = e0 + e1;
            ETt[swz(c, R)] = pack_h2(e0, e1);
            const float n0 = a2s[c] * (x0[q] - mean0) * rv0 + b2s[c];
            const float n1 = a2s[c] * (x1[q] - mean1) * rv1 + b2s[c];
            XNt[swz(c, R)] = pack_h2(n0, n1);
        }
#pragma unroll
        for (int q = 0; q < 8; q++) {
            pc[q] += __shfl_xor_sync(0xFFFFFFFFu, pc[q], 8);
            pc[q] += __shfl_xor_sync(0xFFFFFFFFu, pc[q], 16);
        }
        if (lane < 8) {
#pragma unroll
            for (int q = 0; q < 8; q++) {
                const int c = 4*lane + (q & 3) + (q >> 2) * 32;
                Sp[tile*512 + warp*64 + c] = pc[q];
            }
        }
    }
    __syncthreads();

    // ---- Sinv ----
    if (t < 128) {
        const int tl = t >> 6, i = t & 63;
        float s = 0.f;
#pragma unroll
        for (int w = 0; w < 8; w++) s += Sp[tl*512 + w*64 + i];
        Si[tl*64 + i] = 1.0f / s;
    }
    __syncthreads();

    // ---- GEMMs: warps 0-3 tile0, 4-7 tile1; each warp 32x32 output ----
    const int tile = warp >> 2;
    const int wq   = warp & 3;
    const int i0w  = (wq & 1) * 32;
    const int j0w  = (wq >> 1) * 32;
    const int g    = lane >> 2;
    const int tg   = lane & 3;

    const int rl = lane & 15;
    const int kb = (lane >> 4) * 4;

    const uint32_t etB = smb + OF_ET + tile * 8192;   // ET for GEMM1, ND for GEMM2
    const uint32_t xnB = smb + OF_XN + tile * 8192;
    const uint32_t wtB = smb + OF_WT;

    uint32_t adrA[2], adrB[2];
#pragma unroll
    for (int mt = 0; mt < 2; mt++) adrA[mt] = etB + swzb(i0w + 16*mt + rl, kb);
#pragma unroll
    for (int h = 0; h < 2; h++)    adrB[h]  = xnB + swzb(j0w + 16*h + rl, kb);

    float acc[2][4][4];
#pragma unroll
    for (int mt = 0; mt < 2; mt++)
#pragma unroll
        for (int nt = 0; nt < 4; nt++)
#pragma unroll
            for (int e = 0; e < 4; e++) acc[mt][nt][e] = 0.f;

    // GEMM1: node_u = E^T @ Xn
#pragma unroll
    for (int s = 0; s < 4; s++) {
        const uint32_t ax = (uint32_t)(s << 5);   // 8 k-pairs = 32 bytes per step
        uint32_t a[2][4];
#pragma unroll
        for (int mt = 0; mt < 2; mt++)
            ldm_x4(a[mt][0], a[mt][1], a[mt][2], a[mt][3], adrA[mt] ^ ax);
#pragma unroll
        for (int h = 0; h < 2; h++) {
            uint32_t b00, b01, b10, b11;
            ldm_x4(b00, b01, b10, b11, adrB[h] ^ ax);
            mma_f16(acc[0][2*h],     a[0], b00, b10);
            mma_f16(acc[1][2*h],     a[1], b00, b10);
            mma_f16(acc[0][2*h + 1], a[0], b01, b11);
            mma_f16(acc[1][2*h + 1], a[1], b01, b11);
        }
    }

    __syncthreads();   // ALL warps done reading ET -> safe to overlay ND on it

    // scale rows by Sinv, pack node -> ND (overlaying ET region)
#pragma unroll
    for (int mt = 0; mt < 2; mt++) {
        const int i = i0w + 16*mt + g;
        const float sA = Si[tile*64 + i];
        const float sB = Si[tile*64 + i + 8];
#pragma unroll
        for (int nt = 0; nt < 4; nt++) {
            const int jp = (j0w >> 1) + 4*nt + tg;
            ET[tile*2048 + swz(i,     jp)] = pack_h2(acc[mt][nt][0] * sA, acc[mt][nt][1] * sA);
            ET[tile*2048 + swz(i + 8, jp)] = pack_h2(acc[mt][nt][2] * sB, acc[mt][nt][3] * sB);
        }
    }
    __syncthreads();

    // GEMM2: out = relu(node @ W)   (A from ND in ET region)
#pragma unroll
    for (int h = 0; h < 2; h++) adrB[h] = wtB + swzb(j0w + 16*h + rl, kb);

#pragma unroll
    for (int mt = 0; mt < 2; mt++)
#pragma unroll
        for (int nt = 0; nt < 4; nt++)
#pragma unroll
            for (int e = 0; e < 4; e++) acc[mt][nt][e] = 0.f;

#pragma unroll
    for (int s = 0; s < 4; s++) {
        const uint32_t ax = (uint32_t)(s << 5);
        uint32_t a[2][4];
#pragma unroll
        for (int mt = 0; mt < 2; mt++)
            ldm_x4(a[mt][0], a[mt][1], a[mt][2], a[mt][3], adrA[mt] ^ ax);
#pragma unroll
        for (int h = 0; h < 2; h++) {
            uint32_t b00, b01, b10, b11;
            ldm_x4(b00, b01, b10, b11, adrB[h] ^ ax);
            mma_f16(acc[0][2*h],     a[0], b00, b10);
            mma_f16(acc[1][2*h],     a[1], b00, b10);
            mma_f16(acc[0][2*h + 1], a[0], b01, b11);
            mma_f16(acc[1][2*h + 1], a[1], b01, b11);
        }
    }

    // ReLU + store
    float* Ob = out + (size_t)(2 * blockIdx.x + tile) * 4096u;
#pragma unroll
    for (int mt = 0; mt < 2; mt++) {
        const int i = i0w + 16*mt + g;
#pragma unroll
        for (int nt = 0; nt < 4; nt++) {
            const int j = j0w + 8*nt + 2*tg;
            float2 lo, hi;
            lo.x = fmaxf(acc[mt][nt][0], 0.f); lo.y = fmaxf(acc[mt][nt][1], 0.f);
            hi.x = fmaxf(acc[mt][nt][2], 0.f); hi.y = fmaxf(acc[mt][nt][3], 0.f);
            *(float2*)(Ob + i*64 + j)     = lo;
            *(float2*)(Ob + (i+8)*64 + j) = hi;
        }
    }
}

extern "C" void kernel_launch(void* const* d_in, const int* in_sizes, int n_in,
                              void* d_out, int out_size) {
    const float* X  = (const float*)d_in[0];
    const float* W  = (const float*)d_in[1];
    const float* a2 = (const float*)d_in[2];
    const float* b2 = (const float*)d_in[3];
    float* out = (float*)d_out;

    const int nc = in_sizes[0] / 4096;   // 4096 batch tiles of 64x64
    cudaFuncSetAttribute(gnn_fused_kernel, cudaFuncAttributeMaxDynamicSharedMemorySize, SMEM_BYTES);
    gnn_fused_kernel<<<nc / 2, 256, SMEM_BYTES>>>(X, W, a2, b2, out);
}

// round 15
// speedup vs baseline: 1.0077x; 1.0077x over previous
#include <cuda_runtime.h>
#include <cuda_fp16.h>
#include <cstdint>

// GNN_82592221102580 — fused per 64x64 batch tile (nc = 4096):
//   E = exp(X); Sinv[i] = 1/sum_k E[k][i]
//   Xn = LayerNorm(X) (ddof=1)
//   node = diag(Sinv) * (E^T @ Xn)   <- mma.m16n8k16 fp16 (f32 acc)
//   out  = relu(node @ W)            <- mma.m16n8k16 fp16 (f32 acc)
//
// 2 tiles per CTA (256 thr). Warps 0-3 own tile0 END-TO-END, warps 4-7 own
// tile1; the halves sync only via named barriers (bar.sync 1+h, 128), the one
// full __syncthreads() covers the shared W/a2/b2 staging. Operands in
// half2-packed XOR-swizzled buffers; fragment loads via ldmatrix.m8n8.x4.

__device__ __forceinline__ int swz(int i, int kp) {          // word index
    return i * 32 + (kp ^ ((((i >> 3) ^ i) & 7) << 2));
}
__device__ __forceinline__ int swzb(int row, int kp) {       // byte offset
    return row * 128 + 4 * (kp ^ ((((row >> 3) ^ row) & 7) << 2));
}

// pack (lo, hi) -> u32, lo in bits[15:0]. PTX cvt.rn.f16x2.f32 d,a,b puts b low.
__device__ __forceinline__ uint32_t pack_h2(float lo, float hi) {
    uint32_t r;
    asm("cvt.rn.f16x2.f32 %0, %1, %2;" : "=r"(r) : "f"(hi), "f"(lo));
    return r;
}

__device__ __forceinline__ void ldm_x4(uint32_t& r0, uint32_t& r1, uint32_t& r2,
                                       uint32_t& r3, uint32_t addr) {
    asm volatile("ldmatrix.sync.aligned.m8n8.x4.shared.b16 {%0,%1,%2,%3}, [%4];"
                 : "=r"(r0), "=r"(r1), "=r"(r2), "=r"(r3) : "r"(addr));
}

__device__ __forceinline__ void mma_f16(float d[4], const uint32_t a[4],
                                        uint32_t b0, uint32_t b1) {
    asm volatile(
        "mma.sync.aligned.m16n8k16.row.col.f32.f16.f16.f32 "
        "{%0,%1,%2,%3}, {%4,%5,%6,%7}, {%8,%9}, {%0,%1,%2,%3};"
        : "+f"(d[0]), "+f"(d[1]), "+f"(d[2]), "+f"(d[3])
        : "r"(a[0]), "r"(a[1]), "r"(a[2]), "r"(a[3]), "r"(b0), "r"(b1));
}

#define BAR_HALF(h) asm volatile("bar.sync %0, 128;" :: "r"(1 + (h)) : "memory")

// dynamic smem layout (bytes)
#define OF_ET 0          // [2][2048] u32  ET packed; ND overlays after GEMM1
#define OF_XN 16384      // [2][2048] u32  Xn^T packed
#define OF_WT 32768      // [2048]    u32  W^T packed
#define OF_SP 40960      // [2][4][64] f32 colsum partials (per-half, 4 warps)
#define OF_SI 43008      // [2][64]   f32  Sinv
#define OF_A2 43520      // [64] f32
#define OF_B2 43776      // [64] f32
#define SMEM_BYTES 44032

__global__ __launch_bounds__(256, 4) void gnn_fused_kernel(
    const float* __restrict__ X,
    const float* __restrict__ W,
    const float* __restrict__ a2,
    const float* __restrict__ b2,
    float* __restrict__ out)
{
    extern __shared__ __align__(16) char sm[];
    uint32_t* ET = (uint32_t*)(sm + OF_ET);
    uint32_t* XN = (uint32_t*)(sm + OF_XN);
    uint32_t* WT = (uint32_t*)(sm + OF_WT);
    float*    Sp = (float*)(sm + OF_SP);
    float*    Si = (float*)(sm + OF_SI);
    float*   a2s = (float*)(sm + OF_A2);
    float*   b2s = (float*)(sm + OF_B2);

    const uint32_t smb = (uint32_t)__cvta_generic_to_shared(sm);

    const int t    = threadIdx.x;
    const int warp = t >> 5;
    const int lane = t & 31;
    const int h    = warp >> 2;    // half / tile owned by this warp group
    const int wt   = t & 127;      // thread-in-half
    const int ww   = warp & 3;     // warp-in-half

    if (t < 64) { a2s[t] = a2[t]; b2s[t] = b2[t]; }

    // ---- W -> WT (all 256 threads; shared by both halves) ----
    {
        const int R = t >> 3;      // row-pair 0..31
        const int C = t & 7;
        float w0[8], w1[8];
        float4 v;
        v = *(const float4*)(W + (2*R)*64     + 4*C); w0[0]=v.x; w0[1]=v.y; w0[2]=v.z; w0[3]=v.w;
        v = *(const float4*)(W + (2*R)*64 +32 + 4*C); w0[4]=v.x; w0[5]=v.y; w0[6]=v.z; w0[7]=v.w;
        v = *(const float4*)(W + (2*R+1)*64   + 4*C); w1[0]=v.x; w1[1]=v.y; w1[2]=v.z; w1[3]=v.w;
        v = *(const float4*)(W + (2*R+1)*64+32+ 4*C); w1[4]=v.x; w1[5]=v.y; w1[6]=v.z; w1[7]=v.w;
#pragma unroll
        for (int q = 0; q < 8; q++) {
            const int c = 4*C + (q & 3) + (q >> 2) * 32;
            WT[swz(c, R)] = pack_h2(w0[q], w1[q]);
        }
    }
    __syncthreads();   // WT + a2s/b2s visible to everyone; ONLY full barrier

    // ---- Phase A (own tile only): X -> E^T, Xn^T packed + colsum partials ----
    const float* Xb = X + (size_t)(2 * blockIdx.x + h) * 4096u;
    uint32_t* ETt = ET + h * 2048;
    uint32_t* XNt = XN + h * 2048;
    const int C = wt & 7;

    float pc[8];
#pragma unroll
    for (int q = 0; q < 8; q++) pc[q] = 0.f;

#pragma unroll
    for (int p = 0; p < 2; p++) {
        const int R = 16*p + (wt >> 3);    // row-pair 0..31
        float x0[8], x1[8];
        float4 v;
        v = *(const float4*)(Xb + (2*R)*64      + 4*C); x0[0]=v.x; x0[1]=v.y; x0[2]=v.z; x0[3]=v.w;
        v = *(const float4*)(Xb + (2*R)*64 + 32 + 4*C); x0[4]=v.x; x0[5]=v.y; x0[6]=v.z; x0[7]=v.w;
        v = *(const float4*)(Xb + (2*R+1)*64    + 4*C); x1[0]=v.x; x1[1]=v.y; x1[2]=v.z; x1[3]=v.w;
        v = *(const float4*)(Xb + (2*R+1)*64+32 + 4*C); x1[4]=v.x; x1[5]=v.y; x1[6]=v.z; x1[7]=v.w;

        float s0=0.f, ss0=0.f, s1=0.f, ss1=0.f;
#pragma unroll
        for (int q = 0; q < 8; q++) {
            s0 += x0[q]; ss0 += x0[q]*x0[q];
            s1 += x1[q]; ss1 += x1[q]*x1[q];
        }
#pragma unroll
        for (int m = 1; m <= 4; m <<= 1) {       // 8 lanes share a row-pair
            s0  += __shfl_xor_sync(0xFFFFFFFFu, s0,  m);
            ss0 += __shfl_xor_sync(0xFFFFFFFFu, ss0, m);
            s1  += __shfl_xor_sync(0xFFFFFFFFu, s1,  m);
            ss1 += __shfl_xor_sync(0xFFFFFFFFu, ss1, m);
        }
        const float mean0 = s0 * (1.0f/64.0f);
        const float mean1 = s1 * (1.0f/64.0f);
        float var0 = fmaxf((ss0 - 64.0f*mean0*mean0) * (1.0f/63.0f), 0.0f);
        float var1 = fmaxf((ss1 - 64.0f*mean1*mean1) * (1.0f/63.0f), 0.0f);
        const float rv0 = 1.0f / (sqrtf(var0) + 1e-6f);
        const float rv1 = 1.0f / (sqrtf(var1) + 1e-6f);

#pragma unroll
        for (int q = 0; q < 8; q++) {
            const int c = 4*C + (q & 3) + (q >> 2) * 32;
            const float e0 = __expf(x0[q]);
            const float e1 = __expf(x1[q]);
            pc[q] += e0 + e1;
            ETt[swz(c, R)] = pack_h2(e0, e1);
            const float n0 = a2s[c] * (x0[q] - mean0) * rv0 + b2s[c];
            const float n1 = a2s[c] * (x1[q] - mean1) * rv1 + b2s[c];
            XNt[swz(c, R)] = pack_h2(n0, n1);
        }
    }
    // reduce pc across the warp's row-pair groups (lane bits 3-4)
#pragma unroll
    for (int q = 0; q < 8; q++) {
        pc[q] += __shfl_xor_sync(0xFFFFFFFFu, pc[q], 8);
        pc[q] += __shfl_xor_sync(0xFFFFFFFFu, pc[q], 16);
    }
    if (lane < 8) {
#pragma unroll
        for (int q = 0; q < 8; q++) {
            const int c = 4*lane + (q & 3) + (q >> 2) * 32;
            Sp[h*256 + ww*64 + c] = pc[q];
        }
    }
    BAR_HALF(h);

    // ---- Sinv (first 2 warps of the half) ----
    if (wt < 64) {
        float s = Sp[h*256 + wt] + Sp[h*256 + 64 + wt]
                + Sp[h*256 + 128 + wt] + Sp[h*256 + 192 + wt];
        Si[h*64 + wt] = 1.0f / s;
    }
    BAR_HALF(h);

    // ---- GEMMs: warp ww computes 32x32 tile of own half ----
    const int i0w = (ww & 1) * 32;
    const int j0w = (ww >> 1) * 32;
    const int g   = lane >> 2;
    const int tg  = lane & 3;
    const int rl  = lane & 15;
    const int kb  = (lane >> 4) * 4;

    const uint32_t etB = smb + OF_ET + h * 8192;   // ET for GEMM1, ND for GEMM2
    const uint32_t xnB = smb + OF_XN + h * 8192;
    const uint32_t wtB = smb + OF_WT;

    uint32_t adrA[2], adrB[2];
#pragma unroll
    for (int mt = 0; mt < 2; mt++) adrA[mt] = etB + swzb(i0w + 16*mt + rl, kb);
#pragma unroll
    for (int hh = 0; hh < 2; hh++) adrB[hh] = xnB + swzb(j0w + 16*hh + rl, kb);

    float acc[2][4][4];
#pragma unroll
    for (int mt = 0; mt < 2; mt++)
#pragma unroll
        for (int nt = 0; nt < 4; nt++)
#pragma unroll
            for (int e = 0; e < 4; e++) acc[mt][nt][e] = 0.f;

    // GEMM1: node_u = E^T @ Xn
#pragma unroll
    for (int s = 0; s < 4; s++) {
        const uint32_t ax = (uint32_t)(s << 5);   // 8 k-pairs = 32B per step
        uint32_t a[2][4];
#pragma unroll
        for (int mt = 0; mt < 2; mt++)
            ldm_x4(a[mt][0], a[mt][1], a[mt][2], a[mt][3], adrA[mt] ^ ax);
#pragma unroll
        for (int hh = 0; hh < 2; hh++) {
            uint32_t b00, b01, b10, b11;
            ldm_x4(b00, b01, b10, b11, adrB[hh] ^ ax);
            mma_f16(acc[0][2*hh],     a[0], b00, b10);
            mma_f16(acc[1][2*hh],     a[1], b00, b10);
            mma_f16(acc[0][2*hh + 1], a[0], b01, b11);
            mma_f16(acc[1][2*hh + 1], a[1], b01, b11);
        }
    }

    BAR_HALF(h);   // half's warps done reading ET -> overlay ND on it

    // scale rows by Sinv, pack node -> ND (overlaying ET region)
#pragma unroll
    for (int mt = 0; mt < 2; mt++) {
        const int i = i0w + 16*mt + g;
        const float sA = Si[h*64 + i];
        const float sB = Si[h*64 + i + 8];
#pragma unroll
        for (int nt = 0; nt < 4; nt++) {
            const int jp = (j0w >> 1) + 4*nt + tg;
            ET[h*2048 + swz(i,     jp)] = pack_h2(acc[mt][nt][0] * sA, acc[mt][nt][1] * sA);
            ET[h*2048 + swz(i + 8, jp)] = pack_h2(acc[mt][nt][2] * sB, acc[mt][nt][3] * sB);
        }
    }
    BAR_HALF(h);

    // GEMM2: out = relu(node @ W)
#pragma unroll
    for (int hh = 0; hh < 2; hh++) adrB[hh] = wtB + swzb(j0w + 16*hh + rl, kb);

#pragma unroll
    for (int mt = 0; mt < 2; mt++)
#pragma unroll
        for (int nt = 0; nt < 4; nt++)
#pragma unroll
            for (int e = 0; e < 4; e++) acc[mt][nt][e] = 0.f;

#pragma unroll
    for (int s = 0; s < 4; s++) {
        const uint32_t ax = (uint32_t)(s << 5);
        uint32_t a[2][4];
#pragma unroll
        for (int mt = 0; mt < 2; mt++)
            ldm_x4(a[mt][0], a[mt][1], a[mt][2], a[mt][3], adrA[mt] ^ ax);
#pragma unroll
        for (int hh = 0; hh < 2; hh++) {
            uint32_t b00, b01, b10, b11;
            ldm_x4(b00, b01, b10, b11, adrB[hh] ^ ax);
            mma_f16(acc[0][2*hh],     a[0], b00, b10);
            mma_f16(acc[1][2*hh],     a[1], b00, b10);
            mma_f16(acc[0][2*hh + 1], a[0], b01, b11);
            mma_f16(acc[1][2*hh + 1], a[1], b01, b11);
        }
    }

    // ReLU + store
    float* Ob = out + (size_t)(2 * blockIdx.x + h) * 4096u;
#pragma unroll
    for (int mt = 0; mt < 2; mt++) {
        const int i = i0w + 16*mt + g;
#pragma unroll
        for (int nt = 0; nt < 4; nt++) {
            const int j = j0w + 8*nt + 2*tg;
            float2 lo, hi;
            lo.x = fmaxf(acc[mt][nt][0], 0.f); lo.y = fmaxf(acc[mt][nt][1], 0.f);
            hi.x = fmaxf(acc[mt][nt][2], 0.f); hi.y = fmaxf(acc[mt][nt][3], 0.f);
            *(float2*)(Ob + i*64 + j)     = lo;
            *(float2*)(Ob + (i+8)*64 + j) = hi;
        }
    }
}

extern "C" void kernel_launch(void* const* d_in, const int* in_sizes, int n_in,
                              void* d_out, int out_size) {
    const float* X  = (const float*)d_in[0];
    const float* W  = (const float*)d_in[1];
    const float* a2 = (const float*)d_in[2];
    const float* b2 = (const float*)d_in[3];
    float* out = (float*)d_out;

    const int nc = in_sizes[0] / 4096;   // 4096 batch tiles of 64x64
    cudaFuncSetAttribute(gnn_fused_kernel, cudaFuncAttributeMaxDynamicSharedMemorySize, SMEM_BYTES);
    gnn_fused_kernel<<<nc / 2, 256, SMEM_BYTES>>>(X, W, a2, b2, out);
}